// round 1
// baseline (speedup 1.0000x reference)
#include <cuda_runtime.h>
#include <cstdint>
#include <cstddef>

#define B_  32
#define T_  2048
#define D_  512
#define L_  512
#define NG  2048          // 3L gate cols + L candidate cols
#define GW  1536          // w_w column count

// 536 MB scratch for precomputed x-part of preactivations (+bias folded in).
// Layout: g_pre[(b*T + t)*NG + col]
__device__ float g_pre[(size_t)B_ * T_ * NG];
__device__ unsigned int g_bar;

__global__ void init_kernel() { g_bar = 0u; }

// ---------------------------------------------------------------------------
// Phase 1: PRE = X @ W_x + bias     (X: [65536, 512], W_x: [512, 2048])
// W_x rows 0..511 of w_w (cols 0..1535) and m_w (cols 1536..2047).
// ---------------------------------------------------------------------------
__global__ __launch_bounds__(256, 3)
void gemm_pre_kernel(const float* __restrict__ X,
                     const float* __restrict__ ww, const float* __restrict__ wb,
                     const float* __restrict__ mw, const float* __restrict__ mb)
{
    __shared__ float As[16][132];   // A tile, transposed: As[k][m]
    __shared__ float Bs[16][72];    // B tile: Bs[k][n]

    const int n0 = blockIdx.x * 64;
    const int m0 = blockIdx.y * 128;
    const int tid = threadIdx.x;
    const int tx = tid & 15;        // n direction (16 * 4 = 64)
    const int ty = tid >> 4;        // m direction (16 * 8 = 128)

    const float* Bp; int ldb; const float* bias;
    if (n0 < GW) { Bp = ww + n0;        ldb = GW; bias = wb + n0; }
    else         { Bp = mw + (n0 - GW); ldb = L_; bias = mb + (n0 - GW); }

    float acc[8][4];
    #pragma unroll
    for (int i = 0; i < 8; i++)
        #pragma unroll
        for (int j = 0; j < 4; j++) acc[i][j] = 0.f;

    const int arow = tid >> 2;          // 0..63
    const int ak   = (tid & 3) * 4;     // 0,4,8,12
    const int brow = tid >> 4;          // 0..15
    const int bc   = (tid & 15) * 4;    // 0..60

    for (int k0 = 0; k0 < D_; k0 += 16) {
        #pragma unroll
        for (int h = 0; h < 2; h++) {
            int row = arow + h * 64;
            float4 v = *(const float4*)&X[(size_t)(m0 + row) * D_ + k0 + ak];
            As[ak + 0][row] = v.x; As[ak + 1][row] = v.y;
            As[ak + 2][row] = v.z; As[ak + 3][row] = v.w;
        }
        {
            float4 v = *(const float4*)&Bp[(size_t)(k0 + brow) * ldb + bc];
            *(float4*)&Bs[brow][bc] = v;
        }
        __syncthreads();

        #pragma unroll
        for (int kk = 0; kk < 16; kk++) {
            float a[8], bb[4];
            *(float4*)(a)     = *(const float4*)&As[kk][ty * 8];
            *(float4*)(a + 4) = *(const float4*)&As[kk][ty * 8 + 4];
            *(float4*)(bb)    = *(const float4*)&Bs[kk][tx * 4];
            #pragma unroll
            for (int i = 0; i < 8; i++)
                #pragma unroll
                for (int j = 0; j < 4; j++)
                    acc[i][j] += a[i] * bb[j];
        }
        __syncthreads();
    }

    float4 bias4 = *(const float4*)&bias[tx * 4];
    #pragma unroll
    for (int i = 0; i < 8; i++) {
        int r = m0 + ty * 8 + i;
        float4 o;
        o.x = acc[i][0] + bias4.x;
        o.y = acc[i][1] + bias4.y;
        o.z = acc[i][2] + bias4.z;
        o.w = acc[i][3] + bias4.w;
        *(float4*)&g_pre[(size_t)r * NG + n0 + tx * 4] = o;
    }
}

// ---------------------------------------------------------------------------
// Phase 2: persistent recurrent kernel.
// 128 CTAs, CTA bx owns l in [bx*4, bx*4+4) => 16 gate columns (i,f,o,m x 4).
// W_h slice cached in smem for all steps; c kept in registers; h round-trips
// through the hidden-states output buffer; grid sync via monotonic counter.
// ---------------------------------------------------------------------------
#define NCTA 128
#define NTHR 256
// smem: sH[512][36] (h, k-major) + sW[512][20] (Wh cols, k-major) + sRed[256][20]
#define SMEM_FLOATS (512*36 + 512*20 + 256*20)

__device__ __forceinline__ float sigf(float x)     { return 1.f / (1.f + __expf(-x)); }
__device__ __forceinline__ float tanh_fast(float x){ return 2.f / (1.f + __expf(-2.f * x)) - 1.f; }

__global__ __launch_bounds__(NTHR, 1)
void lstm_kernel(const float* __restrict__ h0, const float* __restrict__ c0,
                 const float* __restrict__ ww, const float* __restrict__ mw,
                 float* __restrict__ out)
{
    extern __shared__ float smem[];
    float* sH   = smem;                 // sH[k*36 + b]
    float* sW   = smem + 512 * 36;      // sW[k*20 + j]
    float* sRed = sW + 512 * 20;        // sRed[tid*20 + v]

    const int tid = threadIdx.x;
    const int L0  = blockIdx.x * 4;

    // ---- load W_h slice once: col(j) = (j>>2)*512 + L0 + (j&3), rows 512+k ----
    for (int it = tid; it < 16 * 512; it += NTHR) {
        int k = it >> 4;
        int j = it & 15;
        int g = j >> 2, jl = j & 3;
        float w;
        if (g < 3) w = ww[(size_t)(512 + k) * GW + g * 512 + L0 + jl];
        else       w = mw[(size_t)(512 + k) * L_ + L0 + jl];
        sW[k * 20 + j] = w;
    }

    // dot-product mapping: 8-way K split (warp = K chunk), 4x4 register block
    const int s  = tid >> 5;            // K chunk 0..7 (k in [s*64, s*64+64))
    const int u  = tid & 31;
    const int b0 = (u >> 2) * 4;        // batch block
    const int j0 = (u & 3) * 4;         // column block
    const int kbase = s * 64;

    // epilogue mapping (tid < 128): one (b, l) pair per thread
    const int eb  = tid >> 2;
    const int ejl = tid & 3;
    float c_reg = 0.f;
    float pre_r[4];
    if (tid < 128) {
        c_reg = c0[eb * L_ + L0 + ejl];
        #pragma unroll
        for (int g = 0; g < 4; g++)
            pre_r[g] = g_pre[(size_t)eb * T_ * NG + g * 512 + L0 + ejl];
    }

    // initial sH from h0 [32][512]
    #pragma unroll
    for (int q = 0; q < 16; q++) {
        int fidx = q * 256 + tid;
        int b = fidx >> 7;
        int kf = fidx & 127;
        float4 v = *(const float4*)&h0[b * 512 + kf * 4];
        int kb = kf * 4;
        sH[(kb + 0) * 36 + b] = v.x;
        sH[(kb + 1) * 36 + b] = v.y;
        sH[(kb + 2) * 36 + b] = v.z;
        sH[(kb + 3) * 36 + b] = v.w;
    }

    float* hid  = out;
    float* cell = out + (size_t)B_ * T_ * L_;

    for (int t = 0; t < T_; t++) {
        __syncthreads();    // sH (and on t==0: sW) ready

        // ---- h-part dot product ----
        float acc[4][4];
        #pragma unroll
        for (int i = 0; i < 4; i++)
            #pragma unroll
            for (int j = 0; j < 4; j++) acc[i][j] = 0.f;

        const float* hp = sH + kbase * 36 + b0;
        const float* wp = sW + kbase * 20 + j0;
        #pragma unroll 8
        for (int kk = 0; kk < 64; kk++) {
            float4 hv = *(const float4*)hp;
            float4 wv = *(const float4*)wp;
            acc[0][0] += hv.x * wv.x; acc[0][1] += hv.x * wv.y;
            acc[0][2] += hv.x * wv.z; acc[0][3] += hv.x * wv.w;
            acc[1][0] += hv.y * wv.x; acc[1][1] += hv.y * wv.y;
            acc[1][2] += hv.y * wv.z; acc[1][3] += hv.y * wv.w;
            acc[2][0] += hv.z * wv.x; acc[2][1] += hv.z * wv.y;
            acc[2][2] += hv.z * wv.z; acc[2][3] += hv.z * wv.w;
            acc[3][0] += hv.w * wv.x; acc[3][1] += hv.w * wv.y;
            acc[3][2] += hv.w * wv.z; acc[3][3] += hv.w * wv.w;
            hp += 36; wp += 20;
        }
        #pragma unroll
        for (int i = 0; i < 4; i++) {
            float4 v = make_float4(acc[i][0], acc[i][1], acc[i][2], acc[i][3]);
            *(float4*)&sRed[tid * 20 + i * 4] = v;
        }
        __syncthreads();

        // ---- reduce K chunks + gate epilogue ----
        if (tid < 128) {
            float z[4];
            #pragma unroll
            for (int g = 0; g < 4; g++) {
                float v = 0.f;
                #pragma unroll
                for (int ss = 0; ss < 8; ss++)
                    v += sRed[(ss * 32 + (eb >> 2) * 4 + g) * 20 + (eb & 3) * 4 + ejl];
                z[g] = v + pre_r[g];
            }
            float ig = sigf(z[0]);
            float fg = sigf(z[1]);
            float og = sigf(z[2]);
            float mg = tanh_fast(z[3]);
            c_reg = fg * c_reg + ig * mg;
            float hn = og * tanh_fast(c_reg);
            size_t off = ((size_t)eb * T_ + t) * L_ + L0 + ejl;
            hid[off]  = hn;
            cell[off] = c_reg;
            if (t + 1 < T_) {   // prefetch next step's x-part early
                #pragma unroll
                for (int g = 0; g < 4; g++)
                    pre_r[g] = g_pre[((size_t)eb * T_ + (t + 1)) * NG + g * 512 + L0 + ejl];
            }
        }

        if (t + 1 < T_) {
            // ---- grid barrier (monotonic counter, reset per launch) ----
            __threadfence();
            __syncthreads();
            if (tid == 0) {
                atomicAdd(&g_bar, 1u);
                unsigned target = (unsigned)(t + 1) * NCTA;
                while (*(volatile unsigned*)&g_bar < target) { }
                __threadfence();
            }
            __syncthreads();
            // ---- stage h(t) for next step ----
            #pragma unroll
            for (int q = 0; q < 16; q++) {
                int fidx = q * 256 + tid;
                int b = fidx >> 7;
                int kf = fidx & 127;
                float4 v = *(const float4*)&hid[((size_t)b * T_ + t) * L_ + kf * 4];
                int kb = kf * 4;
                sH[(kb + 0) * 36 + b] = v.x;
                sH[(kb + 1) * 36 + b] = v.y;
                sH[(kb + 2) * 36 + b] = v.z;
                sH[(kb + 3) * 36 + b] = v.w;
            }
        }
    }
}

// ---------------------------------------------------------------------------
extern "C" void kernel_launch(void* const* d_in, const int* in_sizes, int n_in,
                              void* d_out, int out_size)
{
    const float* x  = (const float*)d_in[0];
    const float* h0 = (const float*)d_in[1];
    const float* c0 = (const float*)d_in[2];
    const float* ww = (const float*)d_in[3];
    const float* wb = (const float*)d_in[4];
    const float* mw = (const float*)d_in[5];
    const float* mb = (const float*)d_in[6];
    float* out = (float*)d_out;

    static int smem_set = 0;
    cudaFuncSetAttribute(lstm_kernel,
                         cudaFuncAttributeMaxDynamicSharedMemorySize,
                         SMEM_FLOATS * (int)sizeof(float));
    (void)smem_set;

    init_kernel<<<1, 1>>>();
    gemm_pre_kernel<<<dim3(NG / 64, (B_ * T_) / 128), 256>>>(x, ww, wb, mw, mb);
    lstm_kernel<<<NCTA, NTHR, SMEM_FLOATS * (int)sizeof(float)>>>(h0, c0, ww, mw, out);
}